// round 9
// baseline (speedup 1.0000x reference)
#include <cuda_runtime.h>
#include <cuda_fp16.h>
#include <cstdint>
#include <cstddef>

// out = x[1024,65536] @ W2[2048,65536]^T, W2[o,l*32+c]=W_pos[o,l]*W_chan[o,c].
// fp16 operands / fp32 accum via mma.sync.m16n8k16. B (=W2) fragments built in
// registers (2 HMUL2 each) from per-lane Wc constants + Wp smem broadcast.
// CTA 128x128x256, 16 warps (warp 32x32), 3-slot cp.async (A 64KB + Wp 4KB).

static constexpr int MB = 1024, NO = 2048, LL = 2048, CC = 32;
static constexpr int KK = LL * CC;                  // 65536

__device__ __half g_xh[(size_t)MB * KK];            // fp16 A

__device__ __forceinline__ uint32_t pk(float a, float b) {
    __half2 h = __floats2half2_rn(a, b);
    return *reinterpret_cast<uint32_t*>(&h);
}

__global__ void k_convert(const float4* __restrict__ x4) {
    int i = blockIdx.x * 256 + threadIdx.x;
    float4 v = x4[i];
    uint2 u; u.x = pk(v.x, v.y); u.y = pk(v.z, v.w);
    reinterpret_cast<uint2*>(g_xh)[i] = u;
}

__device__ __forceinline__ uint32_t smem_u32(const void* p) {
    uint32_t a;
    asm("{ .reg .u64 t; cvta.to.shared.u64 t, %1; cvt.u32.u64 %0, t; }" : "=r"(a) : "l"(p));
    return a;
}
__device__ __forceinline__ void cpa16(uint32_t s, const void* g) {
    asm volatile("cp.async.cg.shared.global [%0], [%1], 16;" :: "r"(s), "l"(g) : "memory");
}
#define CP_COMMIT() asm volatile("cp.async.commit_group;" ::: "memory")
#define CP_WAIT(n)  asm volatile("cp.async.wait_group %0;" :: "n"(n) : "memory")

__device__ __forceinline__ void ldsm4(uint32_t* r, uint32_t a) {
    asm volatile("ldmatrix.sync.aligned.m8n8.x4.shared.b16 {%0,%1,%2,%3}, [%4];"
                 : "=r"(r[0]), "=r"(r[1]), "=r"(r[2]), "=r"(r[3]) : "r"(a));
}
__device__ __forceinline__ void mma16816(float* c, const uint32_t* a,
                                         uint32_t b0, uint32_t b1) {
    asm volatile("mma.sync.aligned.m16n8k16.row.col.f32.f16.f16.f32 "
                 "{%0,%1,%2,%3}, {%4,%5,%6,%7}, {%8,%9}, {%0,%1,%2,%3};"
                 : "+f"(c[0]), "+f"(c[1]), "+f"(c[2]), "+f"(c[3])
                 : "r"(a[0]), "r"(a[1]), "r"(a[2]), "r"(a[3]), "r"(b0), "r"(b1));
}
__device__ __forceinline__ uint32_t hmul2(uint32_t a, uint32_t b) {
    uint32_t d;
    asm("mul.rn.f16x2 %0, %1, %2;" : "=r"(d) : "r"(a), "r"(b));
    return d;
}

static constexpr int BM = 128, BN = 128, KT = 256;
static constexpr int NIT = KK / KT;                 // 256
// smem layout (bytes)
static constexpr uint32_t WP_OFF = 0;               // Wp slots: 3 x 4KB (128 rows x 32B)
static constexpr uint32_t WP_STG = 4096;
static constexpr uint32_t A_OFF  = 12288;           // A slots: 3 x 64KB (512B rows)
static constexpr uint32_t A_STG  = 65536;
static constexpr uint32_t SMEM_BYTES = A_OFF + 3 * A_STG;   // 208896

// 16B-chunk swizzle: XOR within each 128B group of the row
__device__ __forceinline__ uint32_t swz(uint32_t chk, uint32_t row) {
    return (chk & ~7u) | ((chk & 7u) ^ (row & 7u));
}

__global__ void __launch_bounds__(512, 1) k_gemm(float* __restrict__ out,
                                                 const float* __restrict__ Wp,
                                                 const float* __restrict__ Wc) {
    extern __shared__ char smem[];
    const uint32_t sb = smem_u32(smem);
    const int t = threadIdx.x;
    const int w = t >> 5, l = t & 31;
    const int m0 = blockIdx.y * BM, n0 = blockIdx.x * BN;
    const int wm = (w >> 2) * 32, wn = (w & 3) * 32;   // 4x4 warp grid, warp 32x32

    // per-lane Wc constants: 4 n-groups x 2 k-parities x 2 half2 (as R8)
    const int c2 = 2 * (l & 3);
    uint32_t wcH[4][2][2];
#pragma unroll
    for (int g = 0; g < 4; ++g) {
        const float* wb = Wc + (size_t)(n0 + wn + g * 8 + (l >> 2)) * CC;
#pragma unroll
        for (int p = 0; p < 2; ++p) {
            const int c = p * 16 + c2;
            wcH[g][p][0] = pk(wb[c], wb[c + 1]);
            wcH[g][p][1] = pk(wb[c + 8], wb[c + 9]);
        }
    }

    // A loader: thread -> row ar=t>>2, quarter aq=t&3, 8 x 16B chunks (512B rows)
    const int ar = t >> 2, aq = t & 3;
    const __half* gA = g_xh + (size_t)(m0 + ar) * KK;
    const uint32_t arx = (uint32_t)(ar & 7);

    auto load_stage = [&](int it, int slot) {
        const uint32_t ab = sb + A_OFF + (uint32_t)slot * A_STG + (uint32_t)ar * 512u;
        const __half* ga = gA + (size_t)it * KT;
#pragma unroll
        for (int i = 0; i < 8; ++i) {
            const uint32_t c = (uint32_t)(aq + 4 * i);
            cpa16(ab + (swz(c, arx) * 16u), ga + c * 8);
        }
        // Wp: 128 rows x 32B per slot; threads 0..255 write one 16B chunk each
        if (t < 256) {
            const int row = t >> 1, hh = t & 1;
            cpa16(sb + WP_OFF + (uint32_t)slot * WP_STG + (uint32_t)(row * 32 + hh * 16),
                  Wp + (size_t)(n0 + row) * LL + (size_t)it * 8 + hh * 4);
        }
    };

    float acc[2][4][4];
#pragma unroll
    for (int i = 0; i < 2; ++i)
#pragma unroll
        for (int j = 0; j < 4; ++j)
#pragma unroll
            for (int k = 0; k < 4; ++k) acc[i][j][k] = 0.f;

    load_stage(0, 0); CP_COMMIT();
    load_stage(1, 1); CP_COMMIT();

    // ldmatrix lane geometry for A (verified R3-R8)
    const int arow_i = (l & 7) + ((l >> 3) & 1) * 8, achk_i = (l >> 4);
    const int wp_row0 = (wn + (l >> 2)) * 32;       // Wp smem byte offset, g=0

    uint32_t af[2][2][4];
    int slotC = 0, slotG = 1, slotP = 2;
    for (int it = 0; it < NIT; ++it) {
        CP_WAIT(1);           // slotC's load complete; next may be in flight
        __syncthreads();

        if (it + 2 < NIT) { load_stage(it + 2, slotP); CP_COMMIT(); }

        const uint32_t ast = sb + A_OFF + (uint32_t)slotC * A_STG;
        const uint32_t wps = sb + WP_OFF + (uint32_t)slotC * WP_STG;

        auto load_afrags = [&](int ksg, int buf) {
#pragma unroll
            for (int mi = 0; mi < 2; ++mi) {
                const uint32_t row = (uint32_t)(wm + mi * 16 + arow_i);
                const uint32_t chk = (uint32_t)(achk_i + ksg * 2);
                ldsm4(af[buf][mi], ast + row * 512u + swz(chk, row) * 16u);
            }
        };

        load_afrags(0, 0);
#pragma unroll
        for (int h = 0; h < 2; ++h) {
            // Wp for this half: 4 l-positions x 4 n-groups
            float wpf[4][4];
#pragma unroll
            for (int g = 0; g < 4; ++g) {
                float4 v;
                asm volatile("ld.shared.v4.f32 {%0,%1,%2,%3}, [%4];"
                             : "=f"(v.x), "=f"(v.y), "=f"(v.z), "=f"(v.w)
                             : "r"(wps + (uint32_t)(wp_row0 + g * 256 + h * 16)));
                wpf[g][0] = v.x; wpf[g][1] = v.y; wpf[g][2] = v.z; wpf[g][3] = v.w;
            }
            uint32_t wph2[4];
#pragma unroll
            for (int ksl = 0; ksl < 8; ++ksl) {
                const int ksg = h * 8 + ksl;
                if (ksg + 1 < KT / 16) load_afrags(ksg + 1, (ksg + 1) & 1);
                const int bu = ksg & 1, p = ksl & 1, lp = ksl >> 1;
#pragma unroll
                for (int g = 0; g < 4; ++g) {
                    if (p == 0) wph2[g] = pk(wpf[g][lp], wpf[g][lp]);
                    const uint32_t b0 = hmul2(wph2[g], wcH[g][p][0]);
                    const uint32_t b1 = hmul2(wph2[g], wcH[g][p][1]);
                    mma16816(acc[0][g], af[bu][0], b0, b1);
                    mma16816(acc[1][g], af[bu][1], b0, b1);
                }
            }
        }

        const int tmp = slotC;
        slotC = slotG; slotG = slotP; slotP = tmp;
    }

#pragma unroll
    for (int mi = 0; mi < 2; ++mi) {
        const int row = m0 + wm + mi * 16 + (l >> 2);
#pragma unroll
        for (int g = 0; g < 4; ++g) {
            const int col = n0 + wn + g * 8 + (l & 3) * 2;
            float2 lo; lo.x = acc[mi][g][0]; lo.y = acc[mi][g][1];
            float2 hi; hi.x = acc[mi][g][2]; hi.y = acc[mi][g][3];
            *reinterpret_cast<float2*>(out + (size_t)row * NO + col) = lo;
            *reinterpret_cast<float2*>(out + (size_t)(row + 8) * NO + col) = hi;
        }
    }
}

extern "C" void kernel_launch(void* const* d_in, const int* in_sizes, int n_in,
                              void* d_out, int out_size) {
    (void)in_sizes; (void)n_in; (void)out_size;
    const float* x  = (const float*)d_in[0];
    const float* Wp = (const float*)d_in[1];
    const float* Wc = (const float*)d_in[2];
    float* out = (float*)d_out;

    k_convert<<<(MB * (KK / 4)) / 256, 256>>>(reinterpret_cast<const float4*>(x));
    cudaFuncSetAttribute(k_gemm, cudaFuncAttributeMaxDynamicSharedMemorySize,
                         (int)SMEM_BYTES);
    dim3 grid(NO / BN, MB / BM);
    k_gemm<<<grid, 512, SMEM_BYTES>>>(out, Wp, Wc);
}

// round 10
// speedup vs baseline: 1.0348x; 1.0348x over previous
#include <cuda_runtime.h>
#include <cuda_fp16.h>
#include <cstdint>
#include <cstddef>

// out = x[1024,65536] @ W2[2048,65536]^T, W2[o,l*32+c]=W_pos[o,l]*W_chan[o,c].
// fp16 operands / fp32 accum via mma.sync.m16n8k16. B (=W2) fragments built in
// registers (2 HMUL2) from per-lane Wc constants x fp16-Wp PRMT broadcasts.
// CTA 128x128x128, 16 warps (warp 32x32), 3-slot cp.async (A 32KB + Wp 1KB).

static constexpr int MB = 1024, NO = 2048, LL = 2048, CC = 32;
static constexpr int KK = LL * CC;                  // 65536

__device__ __half g_xh[(size_t)MB * KK];            // fp16 A
__device__ __half g_wph[(size_t)NO * LL];           // fp16 W_pos (8 MiB)

__device__ __forceinline__ uint32_t pk(float a, float b) {
    __half2 h = __floats2half2_rn(a, b);
    return *reinterpret_cast<uint32_t*>(&h);
}

__global__ void k_convert(const float4* __restrict__ x4) {
    int i = blockIdx.x * 256 + threadIdx.x;
    float4 v = x4[i];
    uint2 u; u.x = pk(v.x, v.y); u.y = pk(v.z, v.w);
    reinterpret_cast<uint2*>(g_xh)[i] = u;
}

__global__ void k_wph(const float4* __restrict__ wp4) {
    int i = blockIdx.x * 256 + threadIdx.x;
    float4 v = wp4[i];
    uint2 u; u.x = pk(v.x, v.y); u.y = pk(v.z, v.w);
    reinterpret_cast<uint2*>(g_wph)[i] = u;
}

__device__ __forceinline__ uint32_t smem_u32(const void* p) {
    uint32_t a;
    asm("{ .reg .u64 t; cvta.to.shared.u64 t, %1; cvt.u32.u64 %0, t; }" : "=r"(a) : "l"(p));
    return a;
}
__device__ __forceinline__ void cpa16(uint32_t s, const void* g) {
    asm volatile("cp.async.cg.shared.global [%0], [%1], 16;" :: "r"(s), "l"(g) : "memory");
}
__device__ __forceinline__ void cpa8(uint32_t s, const void* g) {
    asm volatile("cp.async.ca.shared.global [%0], [%1], 8;" :: "r"(s), "l"(g) : "memory");
}
#define CP_COMMIT() asm volatile("cp.async.commit_group;" ::: "memory")
#define CP_WAIT(n)  asm volatile("cp.async.wait_group %0;" :: "n"(n) : "memory")

__device__ __forceinline__ void ldsm4(uint32_t* r, uint32_t a) {
    asm volatile("ldmatrix.sync.aligned.m8n8.x4.shared.b16 {%0,%1,%2,%3}, [%4];"
                 : "=r"(r[0]), "=r"(r[1]), "=r"(r[2]), "=r"(r[3]) : "r"(a));
}
__device__ __forceinline__ void mma16816(float* c, const uint32_t* a,
                                         uint32_t b0, uint32_t b1) {
    asm volatile("mma.sync.aligned.m16n8k16.row.col.f32.f16.f16.f32 "
                 "{%0,%1,%2,%3}, {%4,%5,%6,%7}, {%8,%9}, {%0,%1,%2,%3};"
                 : "+f"(c[0]), "+f"(c[1]), "+f"(c[2]), "+f"(c[3])
                 : "r"(a[0]), "r"(a[1]), "r"(a[2]), "r"(a[3]), "r"(b0), "r"(b1));
}
__device__ __forceinline__ uint32_t hmul2(uint32_t a, uint32_t b) {
    uint32_t d;
    asm("mul.rn.f16x2 %0, %1, %2;" : "=r"(d) : "r"(a), "r"(b));
    return d;
}
__device__ __forceinline__ uint32_t prmt1(uint32_t a, uint32_t sel) {
    uint32_t d;
    asm("prmt.b32 %0, %1, %1, %2;" : "=r"(d) : "r"(a), "r"(sel));
    return d;
}

static constexpr int BM = 128, BN = 128, KT = 128;
static constexpr int NIT = KK / KT;                 // 512
// smem layout (bytes)
static constexpr uint32_t WP_OFF = 0;               // Wp slots: 3 x 1KB (128 rows x 8B fp16)
static constexpr uint32_t WP_STG = 1024;
static constexpr uint32_t A_OFF  = 3072;            // A slots: 3 x 32KB (256B rows)
static constexpr uint32_t A_STG  = 32768;
static constexpr uint32_t SMEM_BYTES = A_OFF + 3 * A_STG;   // 101376

// 16B-chunk swizzle for 256B rows: XOR within each 128B half
__device__ __forceinline__ uint32_t swz(uint32_t chk, uint32_t row) {
    return (chk & 8u) | ((chk & 7u) ^ (row & 7u));
}

__global__ void __launch_bounds__(512, 1) k_gemm(float* __restrict__ out,
                                                 const float* __restrict__ Wc) {
    extern __shared__ char smem[];
    const uint32_t sb = smem_u32(smem);
    const int t = threadIdx.x;
    const int w = t >> 5, l = t & 31;
    const int m0 = blockIdx.y * BM, n0 = blockIdx.x * BN;
    const int wm = (w >> 2) * 32, wn = (w & 3) * 32;   // 4x4 warp grid, warp 32x32

    // per-lane Wc constants: 4 n-groups x 2 k-parities x 2 half2 (verified R8)
    const int c2 = 2 * (l & 3);
    uint32_t wcH[4][2][2];
#pragma unroll
    for (int g = 0; g < 4; ++g) {
        const float* wb = Wc + (size_t)(n0 + wn + g * 8 + (l >> 2)) * CC;
#pragma unroll
        for (int p = 0; p < 2; ++p) {
            const int c = p * 16 + c2;
            wcH[g][p][0] = pk(wb[c], wb[c + 1]);
            wcH[g][p][1] = pk(wb[c + 8], wb[c + 9]);
        }
    }

    // A loader geometry (as R8)
    const int ar = t >> 2, aq = t & 3;
    const __half* gA = g_xh + (size_t)(m0 + ar) * KK;
    const uint32_t arx = (uint32_t)(ar & 7);

    auto load_stage = [&](int it, int slot) {
        const uint32_t ab = sb + A_OFF + (uint32_t)slot * A_STG + (uint32_t)ar * 256u;
        const __half* ga = gA + (size_t)it * KT;
#pragma unroll
        for (int i = 0; i < 4; ++i) {
            const uint32_t c = (uint32_t)(aq + 4 * i);
            cpa16(ab + (swz(c, arx) * 16u), ga + c * 8);
        }
        // Wp fp16: 128 rows x 4 halves (8B) per slot
        if (t < 128) {
            cpa8(sb + WP_OFF + (uint32_t)slot * WP_STG + (uint32_t)t * 8u,
                 g_wph + (size_t)(n0 + t) * LL + (size_t)it * 4);
        }
    };

    float acc[2][4][4];
#pragma unroll
    for (int i = 0; i < 2; ++i)
#pragma unroll
        for (int j = 0; j < 4; ++j)
#pragma unroll
            for (int k = 0; k < 4; ++k) acc[i][j][k] = 0.f;

    load_stage(0, 0); CP_COMMIT();
    load_stage(1, 1); CP_COMMIT();

    // ldmatrix lane geometry for A (verified R3-R9)
    const int arow_i = (l & 7) + ((l >> 3) & 1) * 8, achk_i = (l >> 4);
    const uint32_t wp_row0 = (uint32_t)((wn + (l >> 2)) * 8);   // Wp byte offset, g=0

    uint32_t af[2][2][4];
    int slotC = 0, slotG = 1, slotP = 2;
    for (int it = 0; it < NIT; ++it) {
        CP_WAIT(1);
        __syncthreads();      // slotC's A + Wp published CTA-wide

        if (it + 2 < NIT) { load_stage(it + 2, slotP); CP_COMMIT(); }

        const uint32_t ast = sb + A_OFF + (uint32_t)slotC * A_STG;
        const uint32_t wps = sb + WP_OFF + (uint32_t)slotC * WP_STG;

        // Wp fp16 words for this k-slice: per g, 4 halves in 2 regs
        uint32_t wpw[4][2];
#pragma unroll
        for (int g = 0; g < 4; ++g) {
            asm volatile("ld.shared.v2.u32 {%0,%1}, [%2];"
                         : "=r"(wpw[g][0]), "=r"(wpw[g][1])
                         : "r"(wps + wp_row0 + (uint32_t)(g * 64)));
        }

        auto load_afrags = [&](int ks, int buf) {
#pragma unroll
            for (int mi = 0; mi < 2; ++mi) {
                const uint32_t row = (uint32_t)(wm + mi * 16 + arow_i);
                const uint32_t chk = (uint32_t)(achk_i + ks * 2);
                ldsm4(af[buf][mi], ast + row * 256u + swz(chk, row) * 16u);
            }
        };

        load_afrags(0, 0);
        uint32_t wph2[4];
#pragma unroll
        for (int ks = 0; ks < KT / 16; ++ks) {
            if (ks + 1 < KT / 16) load_afrags(ks + 1, (ks + 1) & 1);
            const int bu = ks & 1, p = ks & 1, lp = ks >> 1;
            const uint32_t sel = (lp & 1) ? 0x3232u : 0x1010u;
#pragma unroll
            for (int g = 0; g < 4; ++g) {
                if (p == 0) wph2[g] = prmt1(wpw[g][lp >> 1], sel);
                const uint32_t b0 = hmul2(wph2[g], wcH[g][p][0]);
                const uint32_t b1 = hmul2(wph2[g], wcH[g][p][1]);
                mma16816(acc[0][g], af[bu][0], b0, b1);
                mma16816(acc[1][g], af[bu][1], b0, b1);
            }
        }

        const int tmp = slotC;
        slotC = slotG; slotG = slotP; slotP = tmp;
    }

#pragma unroll
    for (int mi = 0; mi < 2; ++mi) {
        const int row = m0 + wm + mi * 16 + (l >> 2);
#pragma unroll
        for (int g = 0; g < 4; ++g) {
            const int col = n0 + wn + g * 8 + (l & 3) * 2;
            float2 lo; lo.x = acc[mi][g][0]; lo.y = acc[mi][g][1];
            float2 hi; hi.x = acc[mi][g][2]; hi.y = acc[mi][g][3];
            *reinterpret_cast<float2*>(out + (size_t)row * NO + col) = lo;
            *reinterpret_cast<float2*>(out + (size_t)(row + 8) * NO + col) = hi;
        }
    }
}

extern "C" void kernel_launch(void* const* d_in, const int* in_sizes, int n_in,
                              void* d_out, int out_size) {
    (void)in_sizes; (void)n_in; (void)out_size;
    const float* x  = (const float*)d_in[0];
    const float* Wp = (const float*)d_in[1];
    const float* Wc = (const float*)d_in[2];
    float* out = (float*)d_out;

    k_convert<<<(MB * (KK / 4)) / 256, 256>>>(reinterpret_cast<const float4*>(x));
    k_wph<<<(NO * (LL / 4)) / 256, 256>>>(reinterpret_cast<const float4*>(Wp));
    cudaFuncSetAttribute(k_gemm, cudaFuncAttributeMaxDynamicSharedMemorySize,
                         (int)SMEM_BYTES);
    dim3 grid(NO / BN, MB / BM);
    k_gemm<<<grid, 512, SMEM_BYTES>>>(out, Wc);
}

// round 12
// speedup vs baseline: 1.0660x; 1.0302x over previous
#include <cuda_runtime.h>
#include <cuda_fp16.h>
#include <cstdint>
#include <cstddef>

// out = x[1024,65536] @ W2[2048,65536]^T, W2[o,l*32+c]=W_pos[o,l]*W_chan[o,c].
// fp16 operands / fp32 accum via mma.sync.m16n8k16. B (=W2) fragments built in
// registers (2 HMUL2) from per-lane Wc constants x fp16-Wp PRMT broadcasts.
// CTA 64x128x128, 8 warps (warp 32x32), 2 CTAs/SM for cross-CTA latency hiding.
// (R11 fix: A loader loads all 16 x 16B chunks per 256B row.)

static constexpr int MB = 1024, NO = 2048, LL = 2048, CC = 32;
static constexpr int KK = LL * CC;                  // 65536

__device__ __half g_xh[(size_t)MB * KK];            // fp16 A
__device__ __half g_wph[(size_t)NO * LL];           // fp16 W_pos (8 MiB)

__device__ __forceinline__ uint32_t pk(float a, float b) {
    __half2 h = __floats2half2_rn(a, b);
    return *reinterpret_cast<uint32_t*>(&h);
}

__global__ void k_convert(const float4* __restrict__ x4) {
    int i = blockIdx.x * 256 + threadIdx.x;
    float4 v = x4[i];
    uint2 u; u.x = pk(v.x, v.y); u.y = pk(v.z, v.w);
    reinterpret_cast<uint2*>(g_xh)[i] = u;
}

__global__ void k_wph(const float4* __restrict__ wp4) {
    int i = blockIdx.x * 256 + threadIdx.x;
    float4 v = wp4[i];
    uint2 u; u.x = pk(v.x, v.y); u.y = pk(v.z, v.w);
    reinterpret_cast<uint2*>(g_wph)[i] = u;
}

__device__ __forceinline__ uint32_t smem_u32(const void* p) {
    uint32_t a;
    asm("{ .reg .u64 t; cvta.to.shared.u64 t, %1; cvt.u32.u64 %0, t; }" : "=r"(a) : "l"(p));
    return a;
}
__device__ __forceinline__ void cpa16(uint32_t s, const void* g) {
    asm volatile("cp.async.cg.shared.global [%0], [%1], 16;" :: "r"(s), "l"(g) : "memory");
}
__device__ __forceinline__ void cpa8(uint32_t s, const void* g) {
    asm volatile("cp.async.ca.shared.global [%0], [%1], 8;" :: "r"(s), "l"(g) : "memory");
}
#define CP_COMMIT() asm volatile("cp.async.commit_group;" ::: "memory")
#define CP_WAIT(n)  asm volatile("cp.async.wait_group %0;" :: "n"(n) : "memory")

__device__ __forceinline__ void ldsm4(uint32_t* r, uint32_t a) {
    asm volatile("ldmatrix.sync.aligned.m8n8.x4.shared.b16 {%0,%1,%2,%3}, [%4];"
                 : "=r"(r[0]), "=r"(r[1]), "=r"(r[2]), "=r"(r[3]) : "r"(a));
}
__device__ __forceinline__ void mma16816(float* c, const uint32_t* a,
                                         uint32_t b0, uint32_t b1) {
    asm volatile("mma.sync.aligned.m16n8k16.row.col.f32.f16.f16.f32 "
                 "{%0,%1,%2,%3}, {%4,%5,%6,%7}, {%8,%9}, {%0,%1,%2,%3};"
                 : "+f"(c[0]), "+f"(c[1]), "+f"(c[2]), "+f"(c[3])
                 : "r"(a[0]), "r"(a[1]), "r"(a[2]), "r"(a[3]), "r"(b0), "r"(b1));
}
__device__ __forceinline__ uint32_t hmul2(uint32_t a, uint32_t b) {
    uint32_t d;
    asm("mul.rn.f16x2 %0, %1, %2;" : "=r"(d) : "r"(a), "r"(b));
    return d;
}
__device__ __forceinline__ uint32_t prmt1(uint32_t a, uint32_t sel) {
    uint32_t d;
    asm("prmt.b32 %0, %1, %1, %2;" : "=r"(d) : "r"(a), "r"(sel));
    return d;
}

static constexpr int BM = 64, BN = 128, KT = 128;
static constexpr int NIT = KK / KT;                 // 512
// smem layout (bytes)
static constexpr uint32_t WP_OFF = 0;               // Wp slots: 3 x 1KB (128 rows x 8B fp16)
static constexpr uint32_t WP_STG = 1024;
static constexpr uint32_t A_OFF  = 3072;            // A slots: 3 x 16KB (64 rows x 256B)
static constexpr uint32_t A_STG  = 16384;
static constexpr uint32_t SMEM_BYTES = A_OFF + 3 * A_STG;   // 52224 -> 2 CTAs/SM

// 16B-chunk swizzle for 256B rows: XOR within each 128B half
__device__ __forceinline__ uint32_t swz(uint32_t chk, uint32_t row) {
    return (chk & 8u) | ((chk & 7u) ^ (row & 7u));
}

__global__ void __launch_bounds__(256, 2) k_gemm(float* __restrict__ out,
                                                 const float* __restrict__ Wc) {
    extern __shared__ char smem[];
    const uint32_t sb = smem_u32(smem);
    const int t = threadIdx.x;
    const int w = t >> 5, l = t & 31;
    const int m0 = blockIdx.y * BM, n0 = blockIdx.x * BN;
    const int wm = (w >> 2) * 32, wn = (w & 3) * 32;   // 2x4 warp grid, warp 32x32

    // per-lane Wc constants: 4 n-groups x 2 k-parities x 2 half2 (verified R8-R10)
    const int c2 = 2 * (l & 3);
    uint32_t wcH[4][2][2];
#pragma unroll
    for (int g = 0; g < 4; ++g) {
        const float* wb = Wc + (size_t)(n0 + wn + g * 8 + (l >> 2)) * CC;
#pragma unroll
        for (int p = 0; p < 2; ++p) {
            const int c = p * 16 + c2;
            wcH[g][p][0] = pk(wb[c], wb[c + 1]);
            wcH[g][p][1] = pk(wb[c + 8], wb[c + 9]);
        }
    }

    // A loader: 64 rows, 256 threads -> 4 threads/row, 4 x 16B chunks each (16 total/row)
    const int ar = t >> 2, aq = t & 3;
    const __half* gA = g_xh + (size_t)(m0 + ar) * KK;
    const uint32_t arx = (uint32_t)(ar & 7);

    auto load_stage = [&](int it, int slot) {
        const uint32_t ab = sb + A_OFF + (uint32_t)slot * A_STG + (uint32_t)ar * 256u;
        const __half* ga = gA + (size_t)it * KT;
#pragma unroll
        for (int i = 0; i < 4; ++i) {
            const uint32_t c = (uint32_t)(aq + 4 * i);
            cpa16(ab + (swz(c, arx) * 16u), ga + c * 8);
        }
        // Wp fp16: 128 rows x 4 halves (8B) per slot
        if (t < 128) {
            cpa8(sb + WP_OFF + (uint32_t)slot * WP_STG + (uint32_t)t * 8u,
                 g_wph + (size_t)(n0 + t) * LL + (size_t)it * 4);
        }
    };

    float acc[2][4][4];
#pragma unroll
    for (int i = 0; i < 2; ++i)
#pragma unroll
        for (int j = 0; j < 4; ++j)
#pragma unroll
            for (int k = 0; k < 4; ++k) acc[i][j][k] = 0.f;

    load_stage(0, 0); CP_COMMIT();
    load_stage(1, 1); CP_COMMIT();

    // ldmatrix lane geometry for A (verified R3-R10)
    const int arow_i = (l & 7) + ((l >> 3) & 1) * 8, achk_i = (l >> 4);
    const uint32_t wp_row0 = (uint32_t)((wn + (l >> 2)) * 8);   // Wp byte offset, g=0

    uint32_t af[2][2][4];
    int slotC = 0, slotG = 1, slotP = 2;
    for (int it = 0; it < NIT; ++it) {
        CP_WAIT(1);
        __syncthreads();      // slotC's A + Wp published CTA-wide

        if (it + 2 < NIT) { load_stage(it + 2, slotP); CP_COMMIT(); }

        const uint32_t ast = sb + A_OFF + (uint32_t)slotC * A_STG;
        const uint32_t wps = sb + WP_OFF + (uint32_t)slotC * WP_STG;

        // Wp fp16 words for this k-slice: per g, 4 halves in 2 regs
        uint32_t wpw[4][2];
#pragma unroll
        for (int g = 0; g < 4; ++g) {
            asm volatile("ld.shared.v2.u32 {%0,%1}, [%2];"
                         : "=r"(wpw[g][0]), "=r"(wpw[g][1])
                         : "r"(wps + wp_row0 + (uint32_t)(g * 64)));
        }

        auto load_afrags = [&](int ks, int buf) {
#pragma unroll
            for (int mi = 0; mi < 2; ++mi) {
                const uint32_t row = (uint32_t)(wm + mi * 16 + arow_i);
                const uint32_t chk = (uint32_t)(achk_i + ks * 2);
                ldsm4(af[buf][mi], ast + row * 256u + swz(chk, row) * 16u);
            }
        };

        load_afrags(0, 0);
        uint32_t wph2[4];
#pragma unroll
        for (int ks = 0; ks < KT / 16; ++ks) {
            if (ks + 1 < KT / 16) load_afrags(ks + 1, (ks + 1) & 1);
            const int bu = ks & 1, p = ks & 1, lp = ks >> 1;
            const uint32_t sel = (lp & 1) ? 0x3232u : 0x1010u;
#pragma unroll
            for (int g = 0; g < 4; ++g) {
                if (p == 0) wph2[g] = prmt1(wpw[g][lp >> 1], sel);
                const uint32_t b0 = hmul2(wph2[g], wcH[g][p][0]);
                const uint32_t b1 = hmul2(wph2[g], wcH[g][p][1]);
                mma16816(acc[0][g], af[bu][0], b0, b1);
                mma16816(acc[1][g], af[bu][1], b0, b1);
            }
        }

        const int tmp = slotC;
        slotC = slotG; slotG = slotP; slotP = tmp;
    }

#pragma unroll
    for (int mi = 0; mi < 2; ++mi) {
        const int row = m0 + wm + mi * 16 + (l >> 2);
#pragma unroll
        for (int g = 0; g < 4; ++g) {
            const int col = n0 + wn + g * 8 + (l & 3) * 2;
            float2 lo; lo.x = acc[mi][g][0]; lo.y = acc[mi][g][1];
            float2 hi; hi.x = acc[mi][g][2]; hi.y = acc[mi][g][3];
            *reinterpret_cast<float2*>(out + (size_t)row * NO + col) = lo;
            *reinterpret_cast<float2*>(out + (size_t)(row + 8) * NO + col) = hi;
        }
    }
}

extern "C" void kernel_launch(void* const* d_in, const int* in_sizes, int n_in,
                              void* d_out, int out_size) {
    (void)in_sizes; (void)n_in; (void)out_size;
    const float* x  = (const float*)d_in[0];
    const float* Wp = (const float*)d_in[1];
    const float* Wc = (const float*)d_in[2];
    float* out = (float*)d_out;

    k_convert<<<(MB * (KK / 4)) / 256, 256>>>(reinterpret_cast<const float4*>(x));
    k_wph<<<(NO * (LL / 4)) / 256, 256>>>(reinterpret_cast<const float4*>(Wp));
    cudaFuncSetAttribute(k_gemm, cudaFuncAttributeMaxDynamicSharedMemorySize,
                         (int)SMEM_BYTES);
    dim3 grid(NO / BN, MB / BM);
    k_gemm<<<grid, 256, SMEM_BYTES>>>(out, Wc);
}

// round 13
// speedup vs baseline: 1.0872x; 1.0199x over previous
#include <cuda_runtime.h>
#include <cuda_fp16.h>
#include <cstdint>
#include <cstddef>

// out = x[1024,65536] @ W2[2048,65536]^T, W2[o,l*32+c]=W_pos[o,l]*W_chan[o,c].
// fp16 operands / fp32 accum via mma.sync.m16n8k16. B (=W2) fragments built in
// registers and DOUBLE-BUFFERED one ks-step ahead (no hmul2->mma RAW stalls).
// CTA 64x128x128, 8 warps (warp 32x32), 2 CTAs/SM.

static constexpr int MB = 1024, NO = 2048, LL = 2048, CC = 32;
static constexpr int KK = LL * CC;                  // 65536

__device__ __half g_xh[(size_t)MB * KK];            // fp16 A
__device__ __half g_wph[(size_t)NO * LL];           // fp16 W_pos (8 MiB)

__device__ __forceinline__ uint32_t pk(float a, float b) {
    __half2 h = __floats2half2_rn(a, b);
    return *reinterpret_cast<uint32_t*>(&h);
}

__global__ void k_convert(const float4* __restrict__ x4) {
    int i = blockIdx.x * 256 + threadIdx.x;
    float4 v = x4[i];
    uint2 u; u.x = pk(v.x, v.y); u.y = pk(v.z, v.w);
    reinterpret_cast<uint2*>(g_xh)[i] = u;
}

__global__ void k_wph(const float4* __restrict__ wp4) {
    int i = blockIdx.x * 256 + threadIdx.x;
    float4 v = wp4[i];
    uint2 u; u.x = pk(v.x, v.y); u.y = pk(v.z, v.w);
    reinterpret_cast<uint2*>(g_wph)[i] = u;
}

__device__ __forceinline__ uint32_t smem_u32(const void* p) {
    uint32_t a;
    asm("{ .reg .u64 t; cvta.to.shared.u64 t, %1; cvt.u32.u64 %0, t; }" : "=r"(a) : "l"(p));
    return a;
}
__device__ __forceinline__ void cpa16(uint32_t s, const void* g) {
    asm volatile("cp.async.cg.shared.global [%0], [%1], 16;" :: "r"(s), "l"(g) : "memory");
}
__device__ __forceinline__ void cpa8(uint32_t s, const void* g) {
    asm volatile("cp.async.ca.shared.global [%0], [%1], 8;" :: "r"(s), "l"(g) : "memory");
}
#define CP_COMMIT() asm volatile("cp.async.commit_group;" ::: "memory")
#define CP_WAIT(n)  asm volatile("cp.async.wait_group %0;" :: "n"(n) : "memory")

__device__ __forceinline__ void ldsm4(uint32_t* r, uint32_t a) {
    asm volatile("ldmatrix.sync.aligned.m8n8.x4.shared.b16 {%0,%1,%2,%3}, [%4];"
                 : "=r"(r[0]), "=r"(r[1]), "=r"(r[2]), "=r"(r[3]) : "r"(a));
}
__device__ __forceinline__ void mma16816(float* c, const uint32_t* a,
                                         uint32_t b0, uint32_t b1) {
    asm volatile("mma.sync.aligned.m16n8k16.row.col.f32.f16.f16.f32 "
                 "{%0,%1,%2,%3}, {%4,%5,%6,%7}, {%8,%9}, {%0,%1,%2,%3};"
                 : "+f"(c[0]), "+f"(c[1]), "+f"(c[2]), "+f"(c[3])
                 : "r"(a[0]), "r"(a[1]), "r"(a[2]), "r"(a[3]), "r"(b0), "r"(b1));
}
__device__ __forceinline__ uint32_t hmul2(uint32_t a, uint32_t b) {
    uint32_t d;
    asm("mul.rn.f16x2 %0, %1, %2;" : "=r"(d) : "r"(a), "r"(b));
    return d;
}
__device__ __forceinline__ uint32_t prmt1(uint32_t a, uint32_t sel) {
    uint32_t d;
    asm("prmt.b32 %0, %1, %1, %2;" : "=r"(d) : "r"(a), "r"(sel));
    return d;
}

static constexpr int BM = 64, BN = 128, KT = 128;
static constexpr int NIT = KK / KT;                 // 512
// smem layout (bytes)
static constexpr uint32_t WP_OFF = 0;               // Wp slots: 3 x 1KB
static constexpr uint32_t WP_STG = 1024;
static constexpr uint32_t A_OFF  = 3072;            // A slots: 3 x 16KB (64 rows x 256B)
static constexpr uint32_t A_STG  = 16384;
static constexpr uint32_t SMEM_BYTES = A_OFF + 3 * A_STG;   // 52224 -> 2 CTAs/SM

// 16B-chunk swizzle for 256B rows: XOR within each 128B half
__device__ __forceinline__ uint32_t swz(uint32_t chk, uint32_t row) {
    return (chk & 8u) | ((chk & 7u) ^ (row & 7u));
}

__global__ void __launch_bounds__(256, 2) k_gemm(float* __restrict__ out,
                                                 const float* __restrict__ Wc) {
    extern __shared__ char smem[];
    const uint32_t sb = smem_u32(smem);
    const int t = threadIdx.x;
    const int w = t >> 5, l = t & 31;
    const int m0 = blockIdx.y * BM, n0 = blockIdx.x * BN;
    const int wm = (w >> 2) * 32, wn = (w & 3) * 32;   // 2x4 warp grid, warp 32x32

    // per-lane Wc constants: 4 n-groups x 2 k-parities x 2 half2 (verified R8-R12)
    const int c2 = 2 * (l & 3);
    uint32_t wcH[4][2][2];
#pragma unroll
    for (int g = 0; g < 4; ++g) {
        const float* wb = Wc + (size_t)(n0 + wn + g * 8 + (l >> 2)) * CC;
#pragma unroll
        for (int p = 0; p < 2; ++p) {
            const int c = p * 16 + c2;
            wcH[g][p][0] = pk(wb[c], wb[c + 1]);
            wcH[g][p][1] = pk(wb[c + 8], wb[c + 9]);
        }
    }

    // A loader: 64 rows, 4 threads/row, 4 x 16B chunks each (16 chunks per 256B row)
    const int ar = t >> 2, aq = t & 3;
    const __half* gA = g_xh + (size_t)(m0 + ar) * KK;
    const uint32_t arx = (uint32_t)(ar & 7);

    auto load_stage = [&](int it, int slot) {
        const uint32_t ab = sb + A_OFF + (uint32_t)slot * A_STG + (uint32_t)ar * 256u;
        const __half* ga = gA + (size_t)it * KT;
#pragma unroll
        for (int i = 0; i < 4; ++i) {
            const uint32_t c = (uint32_t)(aq + 4 * i);
            cpa16(ab + (swz(c, arx) * 16u), ga + c * 8);
        }
        if (t < 128) {
            cpa8(sb + WP_OFF + (uint32_t)slot * WP_STG + (uint32_t)t * 8u,
                 g_wph + (size_t)(n0 + t) * LL + (size_t)it * 4);
        }
    };

    float acc[2][4][4];
#pragma unroll
    for (int i = 0; i < 2; ++i)
#pragma unroll
        for (int j = 0; j < 4; ++j)
#pragma unroll
            for (int k = 0; k < 4; ++k) acc[i][j][k] = 0.f;

    load_stage(0, 0); CP_COMMIT();
    load_stage(1, 1); CP_COMMIT();

    // ldmatrix lane geometry for A (verified R3-R12)
    const int arow_i = (l & 7) + ((l >> 3) & 1) * 8, achk_i = (l >> 4);
    const uint32_t wp_row0 = (uint32_t)((wn + (l >> 2)) * 8);   // Wp byte offset, g=0

    uint32_t af[2][2][4];
    uint32_t bfrag[2][4][2];
    uint32_t wph2[4];

    int slotC = 0, slotG = 1, slotP = 2;
    for (int it = 0; it < NIT; ++it) {
        CP_WAIT(1);
        __syncthreads();      // slotC's A + Wp published CTA-wide

        if (it + 2 < NIT) { load_stage(it + 2, slotP); CP_COMMIT(); }

        const uint32_t ast = sb + A_OFF + (uint32_t)slotC * A_STG;
        const uint32_t wps = sb + WP_OFF + (uint32_t)slotC * WP_STG;

        // Wp fp16 words for this k-slice: per g, 4 halves in 2 regs
        uint32_t wpw[4][2];
#pragma unroll
        for (int g = 0; g < 4; ++g) {
            asm volatile("ld.shared.v2.u32 {%0,%1}, [%2];"
                         : "=r"(wpw[g][0]), "=r"(wpw[g][1])
                         : "r"(wps + wp_row0 + (uint32_t)(g * 64)));
        }

        auto load_afrags = [&](int ks, int buf) {
#pragma unroll
            for (int mi = 0; mi < 2; ++mi) {
                const uint32_t row = (uint32_t)(wm + mi * 16 + arow_i);
                const uint32_t chk = (uint32_t)(achk_i + ks * 2);
                ldsm4(af[buf][mi], ast + row * 256u + swz(chk, row) * 16u);
            }
        };

        // generate B fragments for ks into buffer buf (PRMT broadcast + 2 HMUL2/g)
        auto gen_bfrag = [&](int ks, int buf) {
            const int p = ks & 1, lp = ks >> 1;
            const uint32_t sel = (lp & 1) ? 0x3232u : 0x1010u;
#pragma unroll
            for (int g = 0; g < 4; ++g) {
                if (p == 0) wph2[g] = prmt1(wpw[g][lp >> 1], sel);
                bfrag[buf][g][0] = hmul2(wph2[g], wcH[g][p][0]);
                bfrag[buf][g][1] = hmul2(wph2[g], wcH[g][p][1]);
            }
        };

        load_afrags(0, 0);
        gen_bfrag(0, 0);
#pragma unroll
        for (int ks = 0; ks < KT / 16; ++ks) {
            const int bu = ks & 1;
            if (ks + 1 < KT / 16) {
                load_afrags(ks + 1, (ks + 1) & 1);
                gen_bfrag(ks + 1, (ks + 1) & 1);
            }
#pragma unroll
            for (int g = 0; g < 4; ++g) {
                mma16816(acc[0][g], af[bu][0], bfrag[bu][g][0], bfrag[bu][g][1]);
                mma16816(acc[1][g], af[bu][1], bfrag[bu][g][0], bfrag[bu][g][1]);
            }
        }

        const int tmp = slotC;
        slotC = slotG; slotG = slotP; slotP = tmp;
    }

#pragma unroll
    for (int mi = 0; mi < 2; ++mi) {
        const int row = m0 + wm + mi * 16 + (l >> 2);
#pragma unroll
        for (int g = 0; g < 4; ++g) {
            const int col = n0 + wn + g * 8 + (l & 3) * 2;
            float2 lo; lo.x = acc[mi][g][0]; lo.y = acc[mi][g][1];
            float2 hi; hi.x = acc[mi][g][2]; hi.y = acc[mi][g][3];
            *reinterpret_cast<float2*>(out + (size_t)row * NO + col) = lo;
            *reinterpret_cast<float2*>(out + (size_t)(row + 8) * NO + col) = hi;
        }
    }
}

extern "C" void kernel_launch(void* const* d_in, const int* in_sizes, int n_in,
                              void* d_out, int out_size) {
    (void)in_sizes; (void)n_in; (void)out_size;
    const float* x  = (const float*)d_in[0];
    const float* Wp = (const float*)d_in[1];
    const float* Wc = (const float*)d_in[2];
    float* out = (float*)d_out;

    k_convert<<<(MB * (KK / 4)) / 256, 256>>>(reinterpret_cast<const float4*>(x));
    k_wph<<<(NO * (LL / 4)) / 256, 256>>>(reinterpret_cast<const float4*>(Wp));
    cudaFuncSetAttribute(k_gemm, cudaFuncAttributeMaxDynamicSharedMemorySize,
                         (int)SMEM_BYTES);
    dim3 grid(NO / BN, MB / BM);
    k_gemm<<<grid, 256, SMEM_BYTES>>>(out, Wc);
}